// round 1
// baseline (speedup 1.0000x reference)
#include <cuda_runtime.h>
#include <cuda_fp16.h>
#include <mma.h>

using namespace nvcuda;

#define T_TOK 8192
#define D_DIM 1024
#define H_DIM 4096
#define E_NUM 8
#define NPAIR (T_TOK * 2)

// ---------------- scratch (__device__ globals; no allocation) ----------------
__device__ __half g_x16[(size_t)T_TOK * D_DIM];            // 16 MB
__device__ __half g_w1h[(size_t)E_NUM * D_DIM * H_DIM];    // 64 MB
__device__ __half g_w2h[(size_t)E_NUM * H_DIM * D_DIM];    // 64 MB
__device__ __half g_h16[(size_t)NPAIR * H_DIM];            // 128 MB
__device__ int    g_counts[E_NUM];
__device__ int    g_cursor[E_NUM];
__device__ int    g_base[E_NUM + 1];
__device__ int    g_tok[NPAIR];
__device__ float  g_gw[NPAIR];
__device__ int    g_tki[T_TOK];
__device__ float2 g_tkw[T_TOK];

// ---------------- small kernels ----------------
__global__ void k_zero() {
    int i = threadIdx.x;
    if (i < E_NUM) { g_counts[i] = 0; g_cursor[i] = 0; }
}

// convert x -> fp16 AND zero the output buffer (same element count T*D)
__global__ void k_conv_x(const float4* __restrict__ x, float4* __restrict__ out, int n4) {
    int i = blockIdx.x * blockDim.x + threadIdx.x;
    if (i < n4) {
        float4 v = x[i];
        __half2* dst = reinterpret_cast<__half2*>(g_x16) + (size_t)i * 2;
        dst[0] = __floats2half2_rn(v.x, v.y);
        dst[1] = __floats2half2_rn(v.z, v.w);
        out[i] = make_float4(0.f, 0.f, 0.f, 0.f);
    }
}

__global__ void k_conv_w(const float4* __restrict__ src, int which, int n4) {
    __half2* dst = which ? reinterpret_cast<__half2*>(g_w2h)
                         : reinterpret_cast<__half2*>(g_w1h);
    int i = blockIdx.x * blockDim.x + threadIdx.x;
    if (i < n4) {
        float4 v = src[i];
        dst[(size_t)i * 2 + 0] = __floats2half2_rn(v.x, v.y);
        dst[(size_t)i * 2 + 1] = __floats2half2_rn(v.z, v.w);
    }
}

// one warp per token: logits = x@Wg + bg, softmax, top-2 (lowest index on tie)
__global__ void k_route(const float* __restrict__ x, const float* __restrict__ Wg,
                        const float* __restrict__ bg) {
    __shared__ float sWg[D_DIM * E_NUM];  // 32 KB
    for (int i = threadIdx.x; i < D_DIM * E_NUM; i += blockDim.x) sWg[i] = Wg[i];
    __syncthreads();

    int warp = threadIdx.x >> 5, lane = threadIdx.x & 31;
    int t = blockIdx.x * 8 + warp;

    float acc[E_NUM];
#pragma unroll
    for (int e = 0; e < E_NUM; e++) acc[e] = 0.f;

    const float* xr = x + (size_t)t * D_DIM;
    for (int d = lane; d < D_DIM; d += 32) {
        float xv = xr[d];
        const float* w = &sWg[d * E_NUM];
#pragma unroll
        for (int e = 0; e < E_NUM; e++) acc[e] += xv * w[e];
    }
#pragma unroll
    for (int e = 0; e < E_NUM; e++) {
#pragma unroll
        for (int off = 16; off; off >>= 1)
            acc[e] += __shfl_xor_sync(0xffffffffu, acc[e], off);
    }

    if (lane == 0) {
        float l[E_NUM];
        float mx = -1e30f;
#pragma unroll
        for (int e = 0; e < E_NUM; e++) { l[e] = acc[e] + bg[e]; mx = fmaxf(mx, l[e]); }
        float p[E_NUM];
        float s = 0.f;
#pragma unroll
        for (int e = 0; e < E_NUM; e++) { p[e] = expf(l[e] - mx); s += p[e]; }
        int e0 = 0;
#pragma unroll
        for (int e = 1; e < E_NUM; e++) if (p[e] > p[e0]) e0 = e;
        int e1 = (e0 == 0) ? 1 : 0;
#pragma unroll
        for (int e = 0; e < E_NUM; e++) if (e != e0 && p[e] > p[e1]) e1 = e;
        float inv = 1.f / s;
        atomicAdd(&g_counts[e0], 1);
        atomicAdd(&g_counts[e1], 1);
        g_tki[t] = e0 | (e1 << 8);
        g_tkw[t] = make_float2(p[e0] * inv, p[e1] * inv);
    }
}

__global__ void k_prefix() {
    if (threadIdx.x == 0) {
        int b = 0;
        for (int e = 0; e < E_NUM; e++) { g_base[e] = b; b += g_counts[e]; }
        g_base[E_NUM] = b;
    }
}

__global__ void k_scatter() {
    int t = blockIdx.x * blockDim.x + threadIdx.x;
    if (t < T_TOK) {
        int pk = g_tki[t];
        float2 w = g_tkw[t];
        int e0 = pk & 255, e1 = (pk >> 8) & 255;
        int p0 = atomicAdd(&g_cursor[e0], 1);
        int r0 = g_base[e0] + p0;
        g_tok[r0] = t; g_gw[r0] = w.x;
        int p1 = atomicAdd(&g_cursor[e1], 1);
        int r1 = g_base[e1] + p1;
        g_tok[r1] = t; g_gw[r1] = w.y;
    }
}

// ---------------- grouped GEMMs (wmma fp16, fp32 accum) ----------------
// CTA tile 64(M) x 64(N), K-chunk 64, 8 warps (2x4), warp = 32Mx16N (2 frags)

#define LDH 80   // half tile leading dim (160 B, mult of 16 B)
#define LDC 72   // float staging leading dim (288 B, mult of 16 B)

__global__ void __launch_bounds__(256) k_gemm1(const float* __restrict__ b1) {
    const int e = blockIdx.z;
    const int cnt = g_counts[e];
    const int m0 = blockIdx.x * 64;
    if (m0 >= cnt) return;
    const int n0 = blockIdx.y * 64;
    const int rbase = g_base[e];

    __shared__ alignas(16) char smem[2 * 64 * LDH * 2];
    __half* sA = reinterpret_cast<__half*>(smem);
    __half* sB = reinterpret_cast<__half*>(smem + 64 * LDH * 2);
    float*  sC = reinterpret_cast<float*>(smem);

    const int tid = threadIdx.x;
    const int lr = tid >> 2;
    const int lc = (tid & 3) << 4;

    const int row = m0 + lr;
    const bool avalid = row < cnt;
    const __half* aptr = nullptr;
    if (avalid) {
        int t = g_tok[rbase + row];
        aptr = g_x16 + (size_t)t * D_DIM;
    }

    const int warp = tid >> 5;
    const int wm = warp >> 2;   // 0..1
    const int wn = warp & 3;    // 0..3

    wmma::fragment<wmma::accumulator, 16, 16, 16, float> c0, c1;
    wmma::fill_fragment(c0, 0.f);
    wmma::fill_fragment(c1, 0.f);

    const uint4 z4 = make_uint4(0u, 0u, 0u, 0u);
    for (int kb = 0; kb < D_DIM; kb += 64) {
        uint4 va0 = z4, va1 = z4;
        if (avalid) {
            const uint4* s = reinterpret_cast<const uint4*>(aptr + kb + lc);
            va0 = s[0]; va1 = s[1];
        }
        *reinterpret_cast<uint4*>(sA + lr * LDH + lc)     = va0;
        *reinterpret_cast<uint4*>(sA + lr * LDH + lc + 8) = va1;

        const uint4* bs = reinterpret_cast<const uint4*>(
            g_w1h + ((size_t)e * D_DIM + kb + lr) * H_DIM + n0 + lc);
        *reinterpret_cast<uint4*>(sB + lr * LDH + lc)     = bs[0];
        *reinterpret_cast<uint4*>(sB + lr * LDH + lc + 8) = bs[1];
        __syncthreads();

#pragma unroll
        for (int kk = 0; kk < 64; kk += 16) {
            wmma::fragment<wmma::matrix_a, 16, 16, 16, __half, wmma::row_major> a0, a1;
            wmma::fragment<wmma::matrix_b, 16, 16, 16, __half, wmma::row_major> bf;
            wmma::load_matrix_sync(a0, sA + (wm * 32) * LDH + kk, LDH);
            wmma::load_matrix_sync(a1, sA + (wm * 32 + 16) * LDH + kk, LDH);
            wmma::load_matrix_sync(bf, sB + kk * LDH + wn * 16, LDH);
            wmma::mma_sync(c0, a0, bf, c0);
            wmma::mma_sync(c1, a1, bf, c1);
        }
        __syncthreads();
    }

    wmma::store_matrix_sync(sC + (wm * 32) * LDC + wn * 16, c0, LDC, wmma::mem_row_major);
    wmma::store_matrix_sync(sC + (wm * 32 + 16) * LDC + wn * 16, c1, LDC, wmma::mem_row_major);
    __syncthreads();

    if (avalid) {
        size_t hrow = (size_t)(rbase + row) * H_DIM + n0;
        __half tmp[16];
#pragma unroll
        for (int j = 0; j < 16; j++) {
            int n = lc + j;
            float v = sC[lr * LDC + n] + b1[e * H_DIM + n0 + n];
            v = 0.5f * v * (1.f + erff(v * 0.70710678118654752f));
            tmp[j] = __float2half(v);
        }
#pragma unroll
        for (int j = 0; j < 2; j++)
            *reinterpret_cast<uint4*>(g_h16 + hrow + lc + j * 8) =
                *reinterpret_cast<uint4*>(tmp + j * 8);
    }
}

__global__ void __launch_bounds__(256) k_gemm2(const float* __restrict__ b2,
                                               float* __restrict__ out) {
    const int e = blockIdx.z;
    const int cnt = g_counts[e];
    const int m0 = blockIdx.x * 64;
    if (m0 >= cnt) return;
    const int n0 = blockIdx.y * 64;
    const int rbase = g_base[e];

    __shared__ alignas(16) char smem[2 * 64 * LDH * 2];
    __half* sA = reinterpret_cast<__half*>(smem);
    __half* sB = reinterpret_cast<__half*>(smem + 64 * LDH * 2);
    float*  sC = reinterpret_cast<float*>(smem);

    const int tid = threadIdx.x;
    const int lr = tid >> 2;
    const int lc = (tid & 3) << 4;

    const int row = m0 + lr;
    const bool avalid = row < cnt;
    const __half* aptr = nullptr;
    if (avalid) aptr = g_h16 + (size_t)(rbase + row) * H_DIM;

    const int warp = tid >> 5;
    const int wm = warp >> 2;
    const int wn = warp & 3;

    wmma::fragment<wmma::accumulator, 16, 16, 16, float> c0, c1;
    wmma::fill_fragment(c0, 0.f);
    wmma::fill_fragment(c1, 0.f);

    const uint4 z4 = make_uint4(0u, 0u, 0u, 0u);
    for (int kb = 0; kb < H_DIM; kb += 64) {
        uint4 va0 = z4, va1 = z4;
        if (avalid) {
            const uint4* s = reinterpret_cast<const uint4*>(aptr + kb + lc);
            va0 = s[0]; va1 = s[1];
        }
        *reinterpret_cast<uint4*>(sA + lr * LDH + lc)     = va0;
        *reinterpret_cast<uint4*>(sA + lr * LDH + lc + 8) = va1;

        const uint4* bs = reinterpret_cast<const uint4*>(
            g_w2h + ((size_t)e * H_DIM + kb + lr) * D_DIM + n0 + lc);
        *reinterpret_cast<uint4*>(sB + lr * LDH + lc)     = bs[0];
        *reinterpret_cast<uint4*>(sB + lr * LDH + lc + 8) = bs[1];
        __syncthreads();

#pragma unroll
        for (int kk = 0; kk < 64; kk += 16) {
            wmma::fragment<wmma::matrix_a, 16, 16, 16, __half, wmma::row_major> a0, a1;
            wmma::fragment<wmma::matrix_b, 16, 16, 16, __half, wmma::row_major> bf;
            wmma::load_matrix_sync(a0, sA + (wm * 32) * LDH + kk, LDH);
            wmma::load_matrix_sync(a1, sA + (wm * 32 + 16) * LDH + kk, LDH);
            wmma::load_matrix_sync(bf, sB + kk * LDH + wn * 16, LDH);
            wmma::mma_sync(c0, a0, bf, c0);
            wmma::mma_sync(c1, a1, bf, c1);
        }
        __syncthreads();
    }

    wmma::store_matrix_sync(sC + (wm * 32) * LDC + wn * 16, c0, LDC, wmma::mem_row_major);
    wmma::store_matrix_sync(sC + (wm * 32 + 16) * LDC + wn * 16, c1, LDC, wmma::mem_row_major);
    __syncthreads();

    if (avalid) {
        const int t = g_tok[rbase + row];
        const float g = g_gw[rbase + row];
        float* orow = out + (size_t)t * D_DIM + n0;
#pragma unroll
        for (int j = 0; j < 16; j++) {
            int n = lc + j;
            float v = (sC[lr * LDC + n] + b2[e * D_DIM + n0 + n]) * g;
            atomicAdd(orow + n, v);
        }
    }
}

// ---------------- launch ----------------
extern "C" void kernel_launch(void* const* d_in, const int* in_sizes, int n_in,
                              void* d_out, int out_size) {
    const float* x  = (const float*)d_in[0];
    const float* Wg = (const float*)d_in[1];
    const float* bg = (const float*)d_in[2];
    const float* W1 = (const float*)d_in[3];
    const float* b1 = (const float*)d_in[4];
    const float* W2 = (const float*)d_in[5];
    const float* b2 = (const float*)d_in[6];
    float* out = (float*)d_out;

    k_zero<<<1, 32>>>();

    int n4x = T_TOK * D_DIM / 4;
    k_conv_x<<<(n4x + 255) / 256, 256>>>((const float4*)x, (float4*)out, n4x);

    int n4w = E_NUM * D_DIM * H_DIM / 4;
    k_conv_w<<<(n4w + 255) / 256, 256>>>((const float4*)W1, 0, n4w);
    k_conv_w<<<(n4w + 255) / 256, 256>>>((const float4*)W2, 1, n4w);

    k_route<<<T_TOK / 8, 256>>>(x, Wg, bg);
    k_prefix<<<1, 1>>>();
    k_scatter<<<T_TOK / 256, 256>>>();

    dim3 g1(T_TOK / 64, H_DIM / 64, E_NUM);  // 128 x 64 x 8, early-exit on empty tiles
    k_gemm1<<<g1, 256>>>(b1);

    dim3 g2(T_TOK / 64, D_DIM / 64, E_NUM);  // 128 x 16 x 8
    k_gemm2<<<g2, 256>>>(b2, out);
}

// round 7
// speedup vs baseline: 2.2158x; 2.2158x over previous
#include <cstdint>
#include <cstddef>
#include <cuda_runtime.h>
#include <cuda_fp16.h>
#include <mma.h>

using namespace nvcuda;

#define T_TOK 8192
#define D_DIM 1024
#define H_DIM 4096
#define E_NUM 8
#define MAXT  136
#define MAXROWS (MAXT * 128)

#define BM 128
#define BN 128
#define BK 64
#define NSTG 4
#define LDA 72    // halves
#define LDB 136   // halves
#define LDCF 132  // floats
#define DSMEM (NSTG * (BM * LDA + BK * LDB) * 2)   // 143360 B

// ---------------- scratch ----------------
__device__ __half g_w1h[(size_t)E_NUM * D_DIM * H_DIM];   // 64 MB
__device__ __half g_w2h[(size_t)E_NUM * H_DIM * D_DIM];   // 64 MB
__device__ __half g_ax [(size_t)MAXROWS * D_DIM];         // 35.6 MB gathered x (fp16)
__device__ __half g_hs [(size_t)MAXROWS * H_DIM];         // 142 MB hidden (fp16)
__device__ float  g_part[(size_t)MAXROWS * D_DIM];        // 71 MB partials
__device__ int    g_counts[E_NUM];
__device__ int    g_cursor[E_NUM];
__device__ int    g_basepad[E_NUM];
__device__ int    g_tile_e[MAXT];
__device__ int    g_ntiles;
__device__ int    g_tok[MAXROWS];
__device__ float  g_gw[MAXROWS];
__device__ int    g_slot[T_TOK * 2];
__device__ int    g_tki[T_TOK];
__device__ float2 g_tkw[T_TOK];

__device__ __forceinline__ uint32_t smem_u32(const void* p) {
    uint32_t a;
    asm("{ .reg .u64 t; cvta.to.shared.u64 t, %1; cvt.u32.u64 %0, t; }" : "=r"(a) : "l"(p));
    return a;
}
__device__ __forceinline__ void cp16(uint32_t dst, const void* src) {
    asm volatile("cp.async.cg.shared.global [%0], [%1], 16;" :: "r"(dst), "l"(src));
}
#define CP_COMMIT() asm volatile("cp.async.commit_group;")
#define CP_WAIT(n)  asm volatile("cp.async.wait_group %0;" :: "n"(n))

// ---------------- small kernels ----------------
__global__ void k_init() {
    int i = blockIdx.x * 256 + threadIdx.x;
    if (i < MAXROWS) { g_tok[i] = -1; g_gw[i] = 0.f; }
    if (i < E_NUM) { g_counts[i] = 0; g_cursor[i] = 0; }
}

__global__ void k_convw(const float4* __restrict__ src, int which, int n4) {
    __half2* dst = which ? reinterpret_cast<__half2*>(g_w2h)
                         : reinterpret_cast<__half2*>(g_w1h);
    int i = blockIdx.x * blockDim.x + threadIdx.x;
    if (i < n4) {
        float4 v = src[i];
        dst[(size_t)i * 2 + 0] = __floats2half2_rn(v.x, v.y);
        dst[(size_t)i * 2 + 1] = __floats2half2_rn(v.z, v.w);
    }
}

__global__ void k_route(const float* __restrict__ x, const float* __restrict__ Wg,
                        const float* __restrict__ bg) {
    __shared__ float sWg[D_DIM * E_NUM];
    for (int i = threadIdx.x; i < D_DIM * E_NUM; i += blockDim.x) sWg[i] = Wg[i];
    __syncthreads();
    int warp = threadIdx.x >> 5, lane = threadIdx.x & 31;
    int t = blockIdx.x * 8 + warp;
    float acc[E_NUM];
#pragma unroll
    for (int e = 0; e < E_NUM; e++) acc[e] = 0.f;
    const float* xr = x + (size_t)t * D_DIM;
    for (int d = lane; d < D_DIM; d += 32) {
        float xv = xr[d];
        const float* w = &sWg[d * E_NUM];
#pragma unroll
        for (int e = 0; e < E_NUM; e++) acc[e] += xv * w[e];
    }
#pragma unroll
    for (int e = 0; e < E_NUM; e++)
#pragma unroll
        for (int off = 16; off; off >>= 1)
            acc[e] += __shfl_xor_sync(0xffffffffu, acc[e], off);
    if (lane == 0) {
        float l[E_NUM], mx = -1e30f;
#pragma unroll
        for (int e = 0; e < E_NUM; e++) { l[e] = acc[e] + bg[e]; mx = fmaxf(mx, l[e]); }
        float p[E_NUM], s = 0.f;
#pragma unroll
        for (int e = 0; e < E_NUM; e++) { p[e] = expf(l[e] - mx); s += p[e]; }
        int e0 = 0;
#pragma unroll
        for (int e = 1; e < E_NUM; e++) if (p[e] > p[e0]) e0 = e;
        int e1 = (e0 == 0) ? 1 : 0;
#pragma unroll
        for (int e = 0; e < E_NUM; e++) if (e != e0 && p[e] > p[e1]) e1 = e;
        float inv = 1.f / s;
        atomicAdd(&g_counts[e0], 1);
        atomicAdd(&g_counts[e1], 1);
        g_tki[t] = e0 | (e1 << 8);
        g_tkw[t] = make_float2(p[e0] * inv, p[e1] * inv);
    }
}

__global__ void k_prefix() {
    if (threadIdx.x == 0) {
        int b = 0, ti = 0;
        for (int e = 0; e < E_NUM; e++) {
            g_basepad[e] = b;
            int nt = (g_counts[e] + 127) >> 7;
            for (int i = 0; i < nt; i++) g_tile_e[ti++] = e;
            b += nt << 7;
        }
        g_ntiles = ti;
    }
}

__global__ void k_scatter() {
    int t = blockIdx.x * blockDim.x + threadIdx.x;
    if (t < T_TOK) {
        int pk = g_tki[t];
        float2 w = g_tkw[t];
        int e0 = pk & 255, e1 = (pk >> 8) & 255;
        int r0 = g_basepad[e0] + atomicAdd(&g_cursor[e0], 1);
        g_tok[r0] = t; g_gw[r0] = w.x; g_slot[2 * t] = r0;
        int r1 = g_basepad[e1] + atomicAdd(&g_cursor[e1], 1);
        g_tok[r1] = t; g_gw[r1] = w.y; g_slot[2 * t + 1] = r1;
    }
}

// gather token rows -> plain fp16 rows in g_ax (zeros for padding slots)
__global__ void k_gather(const float* __restrict__ x) {
    int slot = blockIdx.x * 8 + (threadIdx.x >> 5);
    int lane = threadIdx.x & 31;
    int tok = g_tok[slot];
    __half2* dst = reinterpret_cast<__half2*>(g_ax + (size_t)slot * D_DIM);
    if (tok >= 0) {
        const float4* src = reinterpret_cast<const float4*>(x + (size_t)tok * D_DIM);
#pragma unroll
        for (int i = 0; i < 8; i++) {
            float4 v = src[i * 32 + lane];
            dst[i * 64 + lane * 2 + 0] = __floats2half2_rn(v.x, v.y);
            dst[i * 64 + lane * 2 + 1] = __floats2half2_rn(v.z, v.w);
        }
    } else {
        __half2 z = __floats2half2_rn(0.f, 0.f);
#pragma unroll
        for (int i = 0; i < 8; i++) {
            dst[i * 64 + lane * 2 + 0] = z;
            dst[i * 64 + lane * 2 + 1] = z;
        }
    }
}

// ---------------- pipelined HMMA grouped GEMM ----------------
// MODE 1: g_ax[128 rows, K=1024] @ W1[e] -> bias+gelu -> g_hs (fp16)
// MODE 2: g_hs[128 rows, K=4096] @ W2[e] -> (bias)*gw -> g_part (fp32)
template<int MODE>
__global__ void __launch_bounds__(256, 1) k_gemm(const float* __restrict__ bias) {
    constexpr int NS = (MODE == 1) ? H_DIM : D_DIM;
    constexpr int KS = (MODE == 1) ? D_DIM : H_DIM;
    constexpr int KT = KS / BK;

    const int mt = blockIdx.x;
    if (mt >= g_ntiles) return;
    const int nt = blockIdx.y;
    const int n0 = nt * BN;
    const int e = g_tile_e[mt];
    const int tid = threadIdx.x;

    extern __shared__ char smem[];
    __half* sA = (__half*)smem;                         // NSTG stages of 128 x LDA
    __half* sB = (__half*)(smem + (size_t)NSTG * BM * LDA * 2);
    float*  sC = (float*)smem;

    const __half* gA = (MODE == 1) ? (g_ax + (size_t)mt * 128 * D_DIM)
                                   : (g_hs + (size_t)mt * 128 * H_DIM);
    const __half* gB = ((MODE == 1) ? g_w1h : g_w2h) + (size_t)e * KS * NS + n0;
    const uint32_t sAu = smem_u32(sA), sBu = smem_u32(sB);

#define LOAD_STAGE(KSI, S) do {                                                   \
        const __half* ga_ = gA + (KSI) * BK;                                      \
        uint32_t sa_ = sAu + (S) * (BM * LDA * 2);                                \
        _Pragma("unroll")                                                         \
        for (int i_ = 0; i_ < 4; i_++) {                                          \
            int c_ = tid + i_ * 256;                                              \
            int r_ = c_ >> 3, k_ = c_ & 7;                                        \
            cp16(sa_ + r_ * (LDA * 2) + k_ * 16, ga_ + (size_t)r_ * KS + k_ * 8); \
        }                                                                         \
        const __half* gb_ = gB + (size_t)((KSI) * BK) * NS;                       \
        uint32_t sb_ = sBu + (S) * (BK * LDB * 2);                                \
        _Pragma("unroll")                                                         \
        for (int i_ = 0; i_ < 4; i_++) {                                          \
            int c_ = tid + i_ * 256;                                              \
            int r_ = c_ >> 4, k_ = c_ & 15;                                       \
            cp16(sb_ + r_ * (LDB * 2) + k_ * 16, gb_ + (size_t)r_ * NS + k_ * 8); \
        }                                                                         \
        CP_COMMIT();                                                              \
    } while (0)

#pragma unroll
    for (int s = 0; s < NSTG - 1; s++) LOAD_STAGE(s, s);

    const int w = tid >> 5, wm = w & 3, wn = w >> 2;   // warp tile: rows 32*wm, cols 64*wn
    wmma::fragment<wmma::accumulator, 16, 16, 16, float> acc[2][4];
#pragma unroll
    for (int i = 0; i < 2; i++)
#pragma unroll
        for (int j = 0; j < 4; j++) wmma::fill_fragment(acc[i][j], 0.f);

    for (int ks = 0; ks < KT; ks++) {
        int s = ks & (NSTG - 1);
        CP_WAIT(NSTG - 2);
        __syncthreads();
        if (ks + NSTG - 1 < KT) LOAD_STAGE(ks + NSTG - 1, (ks + NSTG - 1) & (NSTG - 1));
        else CP_COMMIT();   // empty group keeps the wait_group arithmetic invariant

        const __half* A = sA + (size_t)s * BM * LDA;
        const __half* B = sB + (size_t)s * BK * LDB;
#pragma unroll
        for (int kk = 0; kk < 4; kk++) {
            wmma::fragment<wmma::matrix_a, 16, 16, 16, __half, wmma::row_major> a0, a1;
            wmma::load_matrix_sync(a0, A + (wm * 32) * LDA + kk * 16, LDA);
            wmma::load_matrix_sync(a1, A + (wm * 32 + 16) * LDA + kk * 16, LDA);
#pragma unroll
            for (int j = 0; j < 4; j++) {
                wmma::fragment<wmma::matrix_b, 16, 16, 16, __half, wmma::row_major> bf;
                wmma::load_matrix_sync(bf, B + (kk * 16) * LDB + wn * 64 + j * 16, LDB);
                wmma::mma_sync(acc[0][j], a0, bf, acc[0][j]);
                wmma::mma_sync(acc[1][j], a1, bf, acc[1][j]);
            }
        }
    }
    CP_WAIT(0);
    __syncthreads();

#pragma unroll
    for (int i = 0; i < 2; i++)
#pragma unroll
        for (int j = 0; j < 4; j++)
            wmma::store_matrix_sync(sC + (wm * 32 + i * 16) * LDCF + wn * 64 + j * 16,
                                    acc[i][j], LDCF, wmma::mem_row_major);
    __syncthreads();

    // elementwise epilogue: thread -> (row = tid/2, 64 cols)
    const int r = tid >> 1;
    const int ch = (tid & 1) * 64;
    const float* crow = sC + r * LDCF + ch;

    if (MODE == 1) {
        const float* bp = bias + (size_t)e * H_DIM + n0 + ch;
        __half hb[64];
#pragma unroll
        for (int c = 0; c < 64; c++) {
            float v = crow[c] + bp[c];
            v = 0.5f * v * (1.f + erff(v * 0.70710678118654752f));
            hb[c] = __float2half(v);
        }
        uint4* dst = (uint4*)(g_hs + (size_t)(mt * 128 + r) * H_DIM + n0 + ch);
#pragma unroll
        for (int u = 0; u < 8; u++) dst[u] = ((uint4*)hb)[u];
    } else {
        const float gw = g_gw[mt * 128 + r];
        const float* bp = bias + (size_t)e * D_DIM + n0 + ch;
        float4* dst = (float4*)(g_part + (size_t)(mt * 128 + r) * D_DIM + n0 + ch);
#pragma unroll
        for (int i = 0; i < 16; i++) {
            float4 v;
            v.x = (crow[i * 4 + 0] + bp[i * 4 + 0]) * gw;
            v.y = (crow[i * 4 + 1] + bp[i * 4 + 1]) * gw;
            v.z = (crow[i * 4 + 2] + bp[i * 4 + 2]) * gw;
            v.w = (crow[i * 4 + 3] + bp[i * 4 + 3]) * gw;
            dst[i] = v;
        }
    }
#undef LOAD_STAGE
}

__global__ void k_combine(float4* __restrict__ out) {
    int idx = blockIdx.x * 256 + threadIdx.x;
    int t = idx >> 8, c = idx & 255;
    const float4* p = (const float4*)g_part;
    float4 a = p[(size_t)g_slot[2 * t] * 256 + c];
    float4 b = p[(size_t)g_slot[2 * t + 1] * 256 + c];
    out[idx] = make_float4(a.x + b.x, a.y + b.y, a.z + b.z, a.w + b.w);
}

// ---------------- launch ----------------
extern "C" void kernel_launch(void* const* d_in, const int* in_sizes, int n_in,
                              void* d_out, int out_size) {
    const float* x  = (const float*)d_in[0];
    const float* Wg = (const float*)d_in[1];
    const float* bg = (const float*)d_in[2];
    const float* W1 = (const float*)d_in[3];
    const float* b1 = (const float*)d_in[4];
    const float* W2 = (const float*)d_in[5];
    const float* b2 = (const float*)d_in[6];
    float* out = (float*)d_out;

    cudaFuncSetAttribute(k_gemm<1>, cudaFuncAttributeMaxDynamicSharedMemorySize, DSMEM);
    cudaFuncSetAttribute(k_gemm<2>, cudaFuncAttributeMaxDynamicSharedMemorySize, DSMEM);

    k_init<<<(MAXROWS + 255) / 256, 256>>>();
    int n4w = E_NUM * D_DIM * H_DIM / 4;
    k_convw<<<(n4w + 255) / 256, 256>>>((const float4*)W1, 0, n4w);
    k_convw<<<(n4w + 255) / 256, 256>>>((const float4*)W2, 1, n4w);
    k_route<<<T_TOK / 8, 256>>>(x, Wg, bg);
    k_prefix<<<1, 32>>>();
    k_scatter<<<T_TOK / 256, 256>>>();
    k_gather<<<MAXROWS / 8, 256>>>(x);

    k_gemm<1><<<dim3(MAXT, H_DIM / BN), 256, DSMEM>>>(b1);
    k_gemm<2><<<dim3(MAXT, D_DIM / BN), 256, DSMEM>>>(b2);

    k_combine<<<T_TOK, 256>>>((float4*)out);
}